// round 7
// baseline (speedup 1.0000x reference)
#include <cuda_runtime.h>
#include <cuda_bf16.h>
#include <cstdint>

#define N_NODES 50000
#define IN_DIM 2000
#define IN_DIM_PAD 2048
#define GRAPH_DIM 512
#define HIDDEN_DIM 256
#define LATENT_DIM 64
#define N_EDGES 1600000
#define BN_EPS 1e-5f

// Scratch (device globals; allocation is forbidden)
__device__ float g_h[(size_t)N_NODES * GRAPH_DIM];
__device__ float g_agg[(size_t)N_NODES * GRAPH_DIM];
__device__ float g_h1[(size_t)N_NODES * HIDDEN_DIM];
__device__ float g_stats0[2 * GRAPH_DIM];
__device__ float g_stats1[2 * HIDDEN_DIM];
__device__ float g_sc0[GRAPH_DIM], g_sh0[GRAPH_DIM];
__device__ float g_sc1[HIDDEN_DIM], g_sh1[HIDDEN_DIM];
// Pre-split x: [N_NODES][IN_DIM_PAD] bf16 hi/lo
__device__ __nv_bfloat16 g_x_hi[(size_t)N_NODES * IN_DIM_PAD];
__device__ __nv_bfloat16 g_x_lo[(size_t)N_NODES * IN_DIM_PAD];
// CSR scratch
__device__ int g_rowcnt[N_NODES];
__device__ int g_rowstart[N_NODES + 1];
__device__ int g_cursor[N_NODES];
__device__ int2 g_edges[N_EDGES];
// Pre-transposed + bf16-split weights: [Nc][Kpad]
__device__ __nv_bfloat16 g_WgT_hi[(size_t)GRAPH_DIM * IN_DIM_PAD];
__device__ __nv_bfloat16 g_WgT_lo[(size_t)GRAPH_DIM * IN_DIM_PAD];
__device__ __nv_bfloat16 g_W1T_hi[(size_t)HIDDEN_DIM * GRAPH_DIM];
__device__ __nv_bfloat16 g_W1T_lo[(size_t)HIDDEN_DIM * GRAPH_DIM];
__device__ __nv_bfloat16 g_WlatT_hi[(size_t)128 * HIDDEN_DIM];
__device__ __nv_bfloat16 g_WlatT_lo[(size_t)128 * HIDDEN_DIM];
__device__ float g_blat[128];

static inline int cdiv(int a, int b) { return (a + b - 1) / b; }

// ---------------------------------------------------------------------------
// PTX helpers
// ---------------------------------------------------------------------------
__device__ __forceinline__ uint32_t smem_u32(const void* p) {
    uint32_t a;
    asm("{ .reg .u64 t; cvta.to.shared.u64 t, %1; cvt.u32.u64 %0, t; }" : "=r"(a) : "l"(p));
    return a;
}
__device__ __forceinline__ void ldsm4(uint32_t* d, uint32_t addr) {
    asm volatile("ldmatrix.sync.aligned.m8n8.x4.shared.b16 {%0,%1,%2,%3}, [%4];"
                 : "=r"(d[0]), "=r"(d[1]), "=r"(d[2]), "=r"(d[3]) : "r"(addr));
}
__device__ __forceinline__ void mma_bf16(float* c, const uint32_t* a, const uint32_t* b) {
    asm volatile(
        "mma.sync.aligned.m16n8k16.row.col.f32.bf16.bf16.f32 "
        "{%0,%1,%2,%3}, {%4,%5,%6,%7}, {%8,%9}, {%0,%1,%2,%3};"
        : "+f"(c[0]), "+f"(c[1]), "+f"(c[2]), "+f"(c[3])
        : "r"(a[0]), "r"(a[1]), "r"(a[2]), "r"(a[3]), "r"(b[0]), "r"(b[1]));
}
__device__ __forceinline__ void cp16(uint32_t dst, const void* src) {
    asm volatile("cp.async.cg.shared.global [%0], [%1], 16;" :: "r"(dst), "l"(src));
}
__device__ __forceinline__ void cp16z(uint32_t dst, const void* src, int sz) {
    asm volatile("cp.async.cg.shared.global [%0], [%1], 16, %2;" :: "r"(dst), "l"(src), "r"(sz));
}
#define CP_COMMIT() asm volatile("cp.async.commit_group;" ::: "memory")
#define CP_WAIT0()  asm volatile("cp.async.wait_group 0;" ::: "memory")
#define CP_WAIT1()  asm volatile("cp.async.wait_group 1;" ::: "memory")

__device__ __forceinline__ uint32_t pack_bf16x2(__nv_bfloat16 lo, __nv_bfloat16 hi) {
    return ((uint32_t)__bfloat16_as_ushort(hi) << 16) | (uint32_t)__bfloat16_as_ushort(lo);
}
__device__ __forceinline__ float softplus_f(float x) {
    return fmaxf(x, 0.f) + log1pf(expf(-fabsf(x)));
}

// ---------------------------------------------------------------------------
// x pre-split: fp32 [N][IN_DIM] -> bf16 hi/lo [N][IN_DIM_PAD], 4 elems/thread
// ---------------------------------------------------------------------------
__global__ void split_x_bf16(const float* __restrict__ x, __nv_bfloat16* __restrict__ Xhi,
                             __nv_bfloat16* __restrict__ Xlo)
{
    long long i4 = (long long)blockIdx.x * blockDim.x + threadIdx.x;
    const long long total4 = (long long)N_NODES * (IN_DIM_PAD / 4);
    if (i4 >= total4) return;
    int r = (int)(i4 / (IN_DIM_PAD / 4));
    int k = (int)(i4 % (IN_DIM_PAD / 4)) * 4;
    float4 v = make_float4(0.f, 0.f, 0.f, 0.f);
    if (k < IN_DIM) v = *(const float4*)&x[(size_t)r * IN_DIM + k];
    __nv_bfloat16 h0 = __float2bfloat16(v.x), h1 = __float2bfloat16(v.y);
    __nv_bfloat16 h2 = __float2bfloat16(v.z), h3 = __float2bfloat16(v.w);
    __nv_bfloat16 l0 = __float2bfloat16(v.x - __bfloat162float(h0));
    __nv_bfloat16 l1 = __float2bfloat16(v.y - __bfloat162float(h1));
    __nv_bfloat16 l2 = __float2bfloat16(v.z - __bfloat162float(h2));
    __nv_bfloat16 l3 = __float2bfloat16(v.w - __bfloat162float(h3));
    size_t o = (size_t)r * IN_DIM_PAD + k;
    *(uint2*)&Xhi[o] = make_uint2(pack_bf16x2(h0, h1), pack_bf16x2(h2, h3));
    *(uint2*)&Xlo[o] = make_uint2(pack_bf16x2(l0, l1), pack_bf16x2(l2, l3));
}

// ---------------------------------------------------------------------------
// Weight transpose + bf16 split
// ---------------------------------------------------------------------------
__global__ void split_w_bf16(const float* __restrict__ W, __nv_bfloat16* __restrict__ Thi,
                             __nv_bfloat16* __restrict__ Tlo, int K, int Nc, int Kpad)
{
    int idx = blockIdx.x * blockDim.x + threadIdx.x;
    if (idx >= Nc * Kpad) return;
    int n = idx / Kpad;
    int k = idx % Kpad;
    float v = (k < K) ? W[(size_t)k * Nc + n] : 0.f;
    __nv_bfloat16 hi = __float2bfloat16(v);
    __nv_bfloat16 lo = __float2bfloat16(v - __bfloat162float(hi));
    Thi[idx] = hi;
    Tlo[idx] = lo;
}

__global__ void concat_bias(const float* __restrict__ b21, const float* __restrict__ b22,
                            float* __restrict__ blat)
{
    int t = threadIdx.x;
    if (t < 64) blat[t] = b21[t];
    else if (t < 128) blat[t] = b22[t - 64];
}

// ---------------------------------------------------------------------------
// Shared GEMM geometry
// ---------------------------------------------------------------------------
#define GBM 128
#define ROWB 80
#define TILEA (GBM * ROWB)   // 10240

// ---------------------------------------------------------------------------
// GEMM1: 3-stage cp.async pipeline, pre-split A (bf16 hi/lo) + pre-split B.
//   C[M,256cols] = (Ahi+Alo)[M,Kpad] @ (Bhi+Blo)^T + bias   (x3: HH+HL+LH)
//   256 threads, 8 warps (2M x 4N), warptile 64x64.
// ---------------------------------------------------------------------------
#define P_BN 256
#define P_BTILE (P_BN * ROWB)                 // 20480
#define P_OB (2 * TILEA)                      // 20480
#define P_STAGE (2 * TILEA + 2 * P_BTILE)     // 61440
#define P_NSTAGE 3
#define P_SMEM (P_NSTAGE * P_STAGE)           // 184320

__global__ void __launch_bounds__(256)
bf16x3_gemm_pre(const __nv_bfloat16* __restrict__ Ahi, const __nv_bfloat16* __restrict__ Alo,
                int Kpad,
                const __nv_bfloat16* __restrict__ Bhi, const __nv_bfloat16* __restrict__ Blo,
                const float* __restrict__ bias, float* __restrict__ C, int ldc, int M)
{
    extern __shared__ char sm[];
    const uint32_t smb = smem_u32(sm);

    const int tid = threadIdx.x;
    const int lane = tid & 31;
    const int wid = tid >> 5;
    const int warpM = wid >> 2;
    const int warpN = wid & 3;
    const int rowBase = blockIdx.y * GBM;
    const int colBase = blockIdx.x * P_BN;
    const int nIter = Kpad / 32;

    float acc[4][8][4];
#pragma unroll
    for (int i = 0; i < 4; i++)
#pragma unroll
        for (int j = 0; j < 8; j++)
#pragma unroll
            for (int v = 0; v < 4; v++) acc[i][j][v] = 0.f;

    // cp.async stage loader: 3072 16B-chunks, 12 per thread
    auto cpStage = [&](int it, int stage) {
        int k0 = it * 32;
        uint32_t sb = smb + stage * P_STAGE;
#pragma unroll
        for (int q = 0; q < 4; q++) {            // A: 1024 chunks
            int ci = tid + q * 256;
            int half = ci >> 9;
            int rowc = ci & 511;
            int row = rowc >> 2;
            int c = rowc & 3;
            int gr = rowBase + row;
            const __nv_bfloat16* src =
                (half ? Alo : Ahi) + (size_t)gr * Kpad + k0 + c * 8;
            uint32_t dst = sb + half * TILEA + row * ROWB + c * 16;
            cp16z(dst, src, (gr < M) ? 16 : 0);
        }
#pragma unroll
        for (int q = 0; q < 8; q++) {            // B: 2048 chunks
            int ci = tid + q * 256;
            int half = ci >> 10;
            int rowc = ci & 1023;
            int row = rowc >> 2;
            int c = rowc & 3;
            const __nv_bfloat16* src =
                (half ? Blo : Bhi) + (size_t)(colBase + row) * Kpad + k0 + c * 8;
            uint32_t dst = sb + P_OB + half * P_BTILE + row * ROWB + c * 16;
            cp16(dst, src);
        }
    };

    const uint32_t aLaneOff = (uint32_t)((lane & 15) * ROWB + ((lane >> 4) << 4));
    const uint32_t bLaneOff = (uint32_t)(((lane & 7) + ((lane & 16) >> 1)) * ROWB
                                         + (((lane >> 3) & 1) << 4));

    cpStage(0, 0); CP_COMMIT();
    cpStage(1, 1); CP_COMMIT();

    for (int it = 0; it < nIter; ++it) {
        const int cur = it % 3;
        CP_WAIT1();
        __syncthreads();
        if (it + 2 < nIter) cpStage(it + 2, (it + 2) % 3);
        CP_COMMIT();   // commit every iter (possibly empty) to keep group counting uniform

        const uint32_t aBase = smb + cur * P_STAGE + warpM * 64 * ROWB + aLaneOff;
        const uint32_t bBase = smb + cur * P_STAGE + P_OB + warpN * 64 * ROWB + bLaneOff;
#pragma unroll
        for (int ks = 0; ks < 2; ks++) {
            const uint32_t kb = ks * 32;
            uint32_t bH[4][4], bL[4][4], aF[4][4];
#pragma unroll
            for (int g = 0; g < 4; g++) {
                ldsm4(bH[g], bBase + g * 16 * ROWB + kb);
                ldsm4(bL[g], bBase + P_BTILE + g * 16 * ROWB + kb);
            }
#pragma unroll
            for (int mt = 0; mt < 4; mt++) ldsm4(aF[mt], aBase + mt * 16 * ROWB + kb);
#pragma unroll
            for (int mt = 0; mt < 4; mt++)
#pragma unroll
                for (int nt = 0; nt < 8; nt++)
                    mma_bf16(acc[mt][nt], aF[mt], &bH[nt >> 1][(nt & 1) * 2]);
#pragma unroll
            for (int mt = 0; mt < 4; mt++)
#pragma unroll
                for (int nt = 0; nt < 8; nt++)
                    mma_bf16(acc[mt][nt], aF[mt], &bL[nt >> 1][(nt & 1) * 2]);
#pragma unroll
            for (int mt = 0; mt < 4; mt++) ldsm4(aF[mt], aBase + TILEA + mt * 16 * ROWB + kb);
#pragma unroll
            for (int mt = 0; mt < 4; mt++)
#pragma unroll
                for (int nt = 0; nt < 8; nt++)
                    mma_bf16(acc[mt][nt], aF[mt], &bH[nt >> 1][(nt & 1) * 2]);
        }
        __syncthreads();
    }

    const int r0 = rowBase + warpM * 64 + (lane >> 2);
    const int c0 = colBase + warpN * 64 + (lane & 3) * 2;
#pragma unroll
    for (int mt = 0; mt < 4; mt++) {
#pragma unroll
        for (int nt = 0; nt < 8; nt++) {
            int r = r0 + mt * 16;
            int c = c0 + nt * 8;
            float b0 = bias[c], b1 = bias[c + 1];
            if (r < M)
                *(float2*)&C[(size_t)r * ldc + c] =
                    make_float2(acc[mt][nt][0] + b0, acc[mt][nt][1] + b1);
            if (r + 8 < M)
                *(float2*)&C[(size_t)(r + 8) * ldc + c] =
                    make_float2(acc[mt][nt][2] + b0, acc[mt][nt][3] + b1);
        }
    }
}

// ---------------------------------------------------------------------------
// bf16x3 GEMM with fp32 A + optional fused BN+softplus loader (R6 version).
// ---------------------------------------------------------------------------
template <int BN>
__global__ void __launch_bounds__(256)
bf16x3_gemm(const float* __restrict__ A, int lda, int Kvalid, int Kpad,
            const __nv_bfloat16* __restrict__ Bhi, const __nv_bfloat16* __restrict__ Blo,
            const float* __restrict__ bias, float* __restrict__ C, int ldc,
            int M, int latent,
            const float* __restrict__ Ascale, const float* __restrict__ Ashift)
{
    constexpr int BTILE = BN * ROWB;
    constexpr int OB = 2 * TILEA;
    constexpr int STAGE = 2 * TILEA + 2 * BTILE;
    constexpr int NT = BN / 32;
    constexpr int NLD = BN / 64;
    constexpr int BCHUNKS = BN / 32;

    extern __shared__ char sm[];
    const uint32_t smb = smem_u32(sm);

    const int tid = threadIdx.x;
    const int lane = tid & 31;
    const int wid = tid >> 5;
    const int warpM = wid >> 2;
    const int warpN = wid & 3;
    const int rowBase = blockIdx.y * GBM;
    const int colBase = blockIdx.x * BN;
    const int nIter = Kpad / 32;
    const bool fuse = (Ascale != nullptr);

    float acc[4][NT][4];
#pragma unroll
    for (int i = 0; i < 4; i++)
#pragma unroll
        for (int j = 0; j < NT; j++)
#pragma unroll
            for (int v = 0; v < 4; v++) acc[i][j][v] = 0.f;

    float4 av[4];
    int arow[4], akq[4];
#pragma unroll
    for (int q = 0; q < 4; q++) {
        int qi = tid + q * 256;
        arow[q] = qi >> 3;
        akq[q] = qi & 7;
    }

    auto loadA = [&](int it) {
        int k0 = it * 32;
#pragma unroll
        for (int q = 0; q < 4; q++) {
            int gr = rowBase + arow[q];
            int k = k0 + akq[q] * 4;
            float4 v = make_float4(0.f, 0.f, 0.f, 0.f);
            if (gr < M) {
                const float* src = A + (size_t)gr * lda + k;
                if (k + 3 < Kvalid) {
                    v = *(const float4*)src;
                    if (fuse) {
                        v.x = softplus_f(v.x * __ldg(&Ascale[k + 0]) + __ldg(&Ashift[k + 0]));
                        v.y = softplus_f(v.y * __ldg(&Ascale[k + 1]) + __ldg(&Ashift[k + 1]));
                        v.z = softplus_f(v.z * __ldg(&Ascale[k + 2]) + __ldg(&Ashift[k + 2]));
                        v.w = softplus_f(v.w * __ldg(&Ascale[k + 3]) + __ldg(&Ashift[k + 3]));
                    }
                } else if (k < Kvalid) {
                    float* vp = &v.x;
#pragma unroll
                    for (int j = 0; j < 4; j++) {
                        if (k + j < Kvalid) {
                            float t = src[j];
                            if (fuse)
                                t = softplus_f(t * __ldg(&Ascale[k + j]) + __ldg(&Ashift[k + j]));
                            vp[j] = t;
                        }
                    }
                }
            }
            av[q] = v;
        }
    };

    auto stsA = [&](int stage) {
        char* sp = sm + stage * STAGE;
#pragma unroll
        for (int q = 0; q < 4; q++) {
            float4 v = av[q];
            __nv_bfloat16 h0 = __float2bfloat16(v.x);
            __nv_bfloat16 h1 = __float2bfloat16(v.y);
            __nv_bfloat16 h2 = __float2bfloat16(v.z);
            __nv_bfloat16 h3 = __float2bfloat16(v.w);
            __nv_bfloat16 l0 = __float2bfloat16(v.x - __bfloat162float(h0));
            __nv_bfloat16 l1 = __float2bfloat16(v.y - __bfloat162float(h1));
            __nv_bfloat16 l2 = __float2bfloat16(v.z - __bfloat162float(h2));
            __nv_bfloat16 l3 = __float2bfloat16(v.w - __bfloat162float(h3));
            uint2 hp = make_uint2(pack_bf16x2(h0, h1), pack_bf16x2(h2, h3));
            uint2 lp = make_uint2(pack_bf16x2(l0, l1), pack_bf16x2(l2, l3));
            int off = arow[q] * ROWB + akq[q] * 8;
            *(uint2*)(sp + off) = hp;
            *(uint2*)(sp + TILEA + off) = lp;
        }
    };

    auto cpB = [&](int it, int stage) {
        int k0 = it * 32;
#pragma unroll
        for (int q = 0; q < BCHUNKS; q++) {
            int ci = tid + q * 256;
            int hilo = ci / (BN * 4);
            int row = (ci >> 2) & (BN - 1);
            int c = ci & 3;
            const __nv_bfloat16* src =
                (hilo ? Blo : Bhi) + (size_t)(colBase + row) * Kpad + k0 + c * 8;
            uint32_t dst = smb + stage * STAGE + OB + hilo * BTILE + row * ROWB + c * 16;
            cp16(dst, src);
        }
    };

    const uint32_t aLaneOff = (uint32_t)((lane & 15) * ROWB + ((lane >> 4) << 4));
    const uint32_t bLaneOff = (uint32_t)(((lane & 7) + ((lane & 16) >> 1)) * ROWB
                                         + (((lane >> 3) & 1) << 4));

    loadA(0);
    cpB(0, 0);
    CP_COMMIT();
    stsA(0);

    for (int it = 0; it < nIter; ++it) {
        const int cur = it & 1;
        const int nxt = cur ^ 1;
        const bool more = (it + 1 < nIter);
        if (more) loadA(it + 1);
        CP_WAIT0();
        __syncthreads();
        if (more) {
            stsA(nxt);
            cpB(it + 1, nxt);
            CP_COMMIT();
        }

        const uint32_t aBase = smb + cur * STAGE + warpM * 64 * ROWB + aLaneOff;
        const uint32_t bBase = smb + cur * STAGE + OB + warpN * (BN / 4) * ROWB + bLaneOff;
#pragma unroll
        for (int ks = 0; ks < 2; ks++) {
            const uint32_t kb = ks * 32;
            uint32_t bH[NLD][4], bL[NLD][4], aF[4][4];
#pragma unroll
            for (int g = 0; g < NLD; g++) {
                ldsm4(bH[g], bBase + g * 16 * ROWB + kb);
                ldsm4(bL[g], bBase + BTILE + g * 16 * ROWB + kb);
            }
#pragma unroll
            for (int mt = 0; mt < 4; mt++) ldsm4(aF[mt], aBase + mt * 16 * ROWB + kb);
#pragma unroll
            for (int mt = 0; mt < 4; mt++)
#pragma unroll
                for (int nt = 0; nt < NT; nt++)
                    mma_bf16(acc[mt][nt], aF[mt], &bH[nt >> 1][(nt & 1) * 2]);
#pragma unroll
            for (int mt = 0; mt < 4; mt++)
#pragma unroll
                for (int nt = 0; nt < NT; nt++)
                    mma_bf16(acc[mt][nt], aF[mt], &bL[nt >> 1][(nt & 1) * 2]);
#pragma unroll
            for (int mt = 0; mt < 4; mt++) ldsm4(aF[mt], aBase + TILEA + mt * 16 * ROWB + kb);
#pragma unroll
            for (int mt = 0; mt < 4; mt++)
#pragma unroll
                for (int nt = 0; nt < NT; nt++)
                    mma_bf16(acc[mt][nt], aF[mt], &bH[nt >> 1][(nt & 1) * 2]);
        }
    }

    const int r0 = rowBase + warpM * 64 + (lane >> 2);
    const int c0 = colBase + warpN * (BN / 4) + (lane & 3) * 2;
#pragma unroll
    for (int mt = 0; mt < 4; mt++) {
#pragma unroll
        for (int nt = 0; nt < NT; nt++) {
            int r = r0 + mt * 16;
            int c = c0 + nt * 8;
            float b0 = bias[c], b1 = bias[c + 1];
            float v0 = acc[mt][nt][0] + b0;
            float v1 = acc[mt][nt][1] + b1;
            float v2 = acc[mt][nt][2] + b0;
            float v3 = acc[mt][nt][3] + b1;
            if (!latent) {
                if (r < M) *(float2*)&C[(size_t)r * ldc + c] = make_float2(v0, v1);
                if (r + 8 < M) *(float2*)&C[(size_t)(r + 8) * ldc + c] = make_float2(v2, v3);
            } else {
                float* base = (c < 64) ? C + c : C + (size_t)N_NODES * 64 + (c - 64);
                if (r < M) *(float2*)&base[(size_t)r * 64] = make_float2(v0, v1);
                if (r + 8 < M) *(float2*)&base[(size_t)(r + 8) * 64] = make_float2(v2, v3);
            }
        }
    }
}

// ---------------------------------------------------------------------------
// Zero kernels
// ---------------------------------------------------------------------------
__global__ void zero_kernel(float4* __restrict__ p, long long n4) {
    long long i = (long long)blockIdx.x * blockDim.x + threadIdx.x;
    long long stride = (long long)gridDim.x * blockDim.x;
    float4 z = make_float4(0.f, 0.f, 0.f, 0.f);
    for (; i < n4; i += stride) p[i] = z;
}
__global__ void zero_int(int* __restrict__ p, int n) {
    int i = blockIdx.x * blockDim.x + threadIdx.x;
    if (i < n) p[i] = 0;
}

// ---------------------------------------------------------------------------
// CSR build: histogram -> scan -> scatter
// ---------------------------------------------------------------------------
__global__ void csr_hist(const int* __restrict__ rows, int* __restrict__ cnt) {
    int e = blockIdx.x * blockDim.x + threadIdx.x;
    if (e < N_EDGES) atomicAdd(&cnt[rows[e]], 1);
}

__global__ void __launch_bounds__(1024)
csr_scan(const int* __restrict__ cnt, int* __restrict__ rowstart, int* __restrict__ cursor)
{
    __shared__ int warpsum[32];
    const int t = threadIdx.x;
    const int CH = (N_NODES + 1023) / 1024;
    const int base = t * CH;

    int s = 0;
    for (int i = 0; i < CH; i++) {
        int idx = base + i;
        if (idx < N_NODES) s += cnt[idx];
    }
    int lane = t & 31, w = t >> 5;
    int v = s;
#pragma unroll
    for (int o = 1; o < 32; o <<= 1) {
        int n = __shfl_up_sync(0xffffffffu, v, o);
        if (lane >= o) v += n;
    }
    if (lane == 31) warpsum[w] = v;
    __syncthreads();
    if (w == 0) {
        int x = warpsum[lane];
#pragma unroll
        for (int o = 1; o < 32; o <<= 1) {
            int n = __shfl_up_sync(0xffffffffu, x, o);
            if (lane >= o) x += n;
        }
        warpsum[lane] = x;
    }
    __syncthreads();
    int run = v - s + (w > 0 ? warpsum[w - 1] : 0);
    for (int i = 0; i < CH; i++) {
        int idx = base + i;
        if (idx < N_NODES) {
            rowstart[idx] = run;
            cursor[idx] = run;
            run += cnt[idx];
        }
    }
    if (t == 1023) rowstart[N_NODES] = N_EDGES;
}

__global__ void csr_scatter(const int* __restrict__ rows, const int* __restrict__ cols,
                            const float* __restrict__ vals, int* __restrict__ cursor,
                            int2* __restrict__ edges)
{
    int e = blockIdx.x * blockDim.x + threadIdx.x;
    if (e >= N_EDGES) return;
    int r = rows[e];
    int p = atomicAdd(&cursor[r], 1);
    edges[p] = make_int2(cols[e], __float_as_int(vals[e]));
}

// ---------------------------------------------------------------------------
// CSR SpMM with smem-staged edges + 4-deep independent gathers.
// ---------------------------------------------------------------------------
__global__ void __launch_bounds__(128)
spmm_csr(const int* __restrict__ rowstart, const int2* __restrict__ edges,
         const float* __restrict__ h, float* __restrict__ agg)
{
    __shared__ int2 se[128];
    const int r = blockIdx.x;
    const int t = threadIdx.x;
    const int s = rowstart[r];
    const int e = rowstart[r + 1];
    const float4* hp = (const float4*)h;

    float4 a0 = make_float4(0.f, 0.f, 0.f, 0.f);
    float4 a1 = make_float4(0.f, 0.f, 0.f, 0.f);
    float4 a2 = make_float4(0.f, 0.f, 0.f, 0.f);
    float4 a3 = make_float4(0.f, 0.f, 0.f, 0.f);

    for (int base = s; base < e; base += 128) {
        const int n = min(128, e - base);
        if (t < n) se[t] = __ldg(&edges[base + t]);
        __syncthreads();

        int i = 0;
        for (; i + 4 <= n; i += 4) {
            int2 e0 = se[i], e1 = se[i + 1], e2 = se[i + 2], e3 = se[i + 3];
            float4 h0 = __ldg(&hp[(size_t)e0.x * 128 + t]);
            float4 h1 = __ldg(&hp[(size_t)e1.x * 128 + t]);
            float4 h2 = __ldg(&hp[(size_t)e2.x * 128 + t]);
            float4 h3 = __ldg(&hp[(size_t)e3.x * 128 + t]);
            float v0 = __int_as_float(e0.y), v1 = __int_as_float(e1.y);
            float v2 = __int_as_float(e2.y), v3 = __int_as_float(e3.y);
            a0.x += v0 * h0.x; a0.y += v0 * h0.y; a0.z += v0 * h0.z; a0.w += v0 * h0.w;
            a1.x += v1 * h1.x; a1.y += v1 * h1.y; a1.z += v1 * h1.z; a1.w += v1 * h1.w;
            a2.x += v2 * h2.x; a2.y += v2 * h2.y; a2.z += v2 * h2.z; a2.w += v2 * h2.w;
            a3.x += v3 * h3.x; a3.y += v3 * h3.y; a3.z += v3 * h3.z; a3.w += v3 * h3.w;
        }
        for (; i < n; i++) {
            int2 e0 = se[i];
            float4 h0 = __ldg(&hp[(size_t)e0.x * 128 + t]);
            float v0 = __int_as_float(e0.y);
            a0.x += v0 * h0.x; a0.y += v0 * h0.y; a0.z += v0 * h0.z; a0.w += v0 * h0.w;
        }
        __syncthreads();
    }

    float4 o;
    o.x = (a0.x + a1.x) + (a2.x + a3.x);
    o.y = (a0.y + a1.y) + (a2.y + a3.y);
    o.z = (a0.z + a1.z) + (a2.z + a3.z);
    o.w = (a0.w + a1.w) + (a2.w + a3.w);
    ((float4*)agg)[(size_t)r * 128 + t] = o;
}

// ---------------------------------------------------------------------------
// Column statistics + BN coefficient computation
// ---------------------------------------------------------------------------
template <int C>
__global__ void colstats(const float* __restrict__ X, float* __restrict__ stats,
                         int Nrows, int rowsPerBlock)
{
    int col = blockIdx.x * blockDim.x + threadIdx.x;
    if (col >= C) return;
    int r0 = blockIdx.y * rowsPerBlock;
    int r1 = min(r0 + rowsPerBlock, Nrows);
    float s = 0.f, s2 = 0.f;
    for (int r = r0; r < r1; r++) {
        float v = X[(size_t)r * C + col];
        s += v;
        s2 += v * v;
    }
    atomicAdd(&stats[col], s);
    atomicAdd(&stats[C + col], s2);
}

template <int C>
__global__ void bn_coeffs(const float* __restrict__ stats, const float* __restrict__ gamma,
                          const float* __restrict__ beta, float* __restrict__ scale,
                          float* __restrict__ shift, int Nrows)
{
    int c = blockIdx.x * blockDim.x + threadIdx.x;
    if (c >= C) return;
    const float invN = 1.f / (float)Nrows;
    float mean = stats[c] * invN;
    float var = stats[C + c] * invN - mean * mean;
    float sc = rsqrtf(var + BN_EPS) * gamma[c];
    scale[c] = sc;
    shift[c] = beta[c] - mean * sc;
}

// ---------------------------------------------------------------------------
// Launcher
// ---------------------------------------------------------------------------
extern "C" void kernel_launch(void* const* d_in, const int* in_sizes, int n_in,
                              void* d_out, int out_size)
{
    const float* x        = (const float*)d_in[0];
    const int*   adj_rows = (const int*)d_in[1];
    const int*   adj_cols = (const int*)d_in[2];
    const float* adj_vals = (const float*)d_in[3];
    const float* Wg  = (const float*)d_in[4];
    const float* bg  = (const float*)d_in[5];
    const float* W1  = (const float*)d_in[6];
    const float* b1  = (const float*)d_in[7];
    const float* W21 = (const float*)d_in[8];
    const float* b21 = (const float*)d_in[9];
    const float* W22 = (const float*)d_in[10];
    const float* b22 = (const float*)d_in[11];
    const float* gamma0 = (const float*)d_in[12];
    const float* beta0  = (const float*)d_in[13];
    const float* gamma1 = (const float*)d_in[14];
    const float* beta1  = (const float*)d_in[15];
    float* out = (float*)d_out;

    float *h, *agg, *h1, *st0, *st1, *blat, *sc0, *sh0, *sc1, *sh1;
    int *rowcnt, *rowstart, *cursor;
    int2 *edges;
    __nv_bfloat16 *x_hi, *x_lo;
    __nv_bfloat16 *wgt_hi, *wgt_lo, *w1t_hi, *w1t_lo, *wlat_hi, *wlat_lo;
    cudaGetSymbolAddress((void**)&h,   g_h);
    cudaGetSymbolAddress((void**)&agg, g_agg);
    cudaGetSymbolAddress((void**)&h1,  g_h1);
    cudaGetSymbolAddress((void**)&st0, g_stats0);
    cudaGetSymbolAddress((void**)&st1, g_stats1);
    cudaGetSymbolAddress((void**)&blat, g_blat);
    cudaGetSymbolAddress((void**)&sc0, g_sc0);
    cudaGetSymbolAddress((void**)&sh0, g_sh0);
    cudaGetSymbolAddress((void**)&sc1, g_sc1);
    cudaGetSymbolAddress((void**)&sh1, g_sh1);
    cudaGetSymbolAddress((void**)&rowcnt, g_rowcnt);
    cudaGetSymbolAddress((void**)&rowstart, g_rowstart);
    cudaGetSymbolAddress((void**)&cursor, g_cursor);
    cudaGetSymbolAddress((void**)&edges, g_edges);
    cudaGetSymbolAddress((void**)&x_hi, g_x_hi);
    cudaGetSymbolAddress((void**)&x_lo, g_x_lo);
    cudaGetSymbolAddress((void**)&wgt_hi, g_WgT_hi);
    cudaGetSymbolAddress((void**)&wgt_lo, g_WgT_lo);
    cudaGetSymbolAddress((void**)&w1t_hi, g_W1T_hi);
    cudaGetSymbolAddress((void**)&w1t_lo, g_W1T_lo);
    cudaGetSymbolAddress((void**)&wlat_hi, g_WlatT_hi);
    cudaGetSymbolAddress((void**)&wlat_lo, g_WlatT_lo);

    constexpr int SMEM128 = 2 * (2 * TILEA + 2 * 128 * ROWB);  //  81920
    constexpr int SMEM256 = 2 * (2 * TILEA + 2 * 256 * ROWB);  // 122880
    cudaFuncSetAttribute(bf16x3_gemm<128>, cudaFuncAttributeMaxDynamicSharedMemorySize, SMEM128);
    cudaFuncSetAttribute(bf16x3_gemm<256>, cudaFuncAttributeMaxDynamicSharedMemorySize, SMEM256);
    cudaFuncSetAttribute(bf16x3_gemm_pre, cudaFuncAttributeMaxDynamicSharedMemorySize, P_SMEM);

    // 0) prep: stats zero, CSR build, split x + weights
    {
        zero_kernel<<<1, 256>>>((float4*)st0, 2 * GRAPH_DIM / 4);
        zero_kernel<<<1, 256>>>((float4*)st1, 2 * HIDDEN_DIM / 4);
        zero_int<<<cdiv(N_NODES, 256), 256>>>(rowcnt, N_NODES);
        csr_hist<<<cdiv(N_EDGES, 256), 256>>>(adj_rows, rowcnt);
        csr_scan<<<1, 1024>>>(rowcnt, rowstart, cursor);
        csr_scatter<<<cdiv(N_EDGES, 256), 256>>>(adj_rows, adj_cols, adj_vals, cursor, edges);

        long long totX4 = (long long)N_NODES * (IN_DIM_PAD / 4);
        split_x_bf16<<<(int)((totX4 + 255) / 256), 256>>>(x, x_hi, x_lo);

        int totWg = GRAPH_DIM * IN_DIM_PAD;
        split_w_bf16<<<cdiv(totWg, 256), 256>>>(Wg, wgt_hi, wgt_lo, IN_DIM, GRAPH_DIM, IN_DIM_PAD);
        int totW1 = HIDDEN_DIM * GRAPH_DIM;
        split_w_bf16<<<cdiv(totW1, 256), 256>>>(W1, w1t_hi, w1t_lo, GRAPH_DIM, HIDDEN_DIM, GRAPH_DIM);
        int totWl = 64 * HIDDEN_DIM;
        split_w_bf16<<<cdiv(totWl, 256), 256>>>(W21, wlat_hi, wlat_lo, HIDDEN_DIM, 64, HIDDEN_DIM);
        split_w_bf16<<<cdiv(totWl, 256), 256>>>(W22, wlat_hi + (size_t)64 * HIDDEN_DIM,
                                                wlat_lo + (size_t)64 * HIDDEN_DIM,
                                                HIDDEN_DIM, 64, HIDDEN_DIM);
        concat_bias<<<1, 128>>>(b21, b22, blat);
    }

    // 1) h = x @ Wg + bg   (pre-split A, 3-stage cp.async pipeline)
    {
        dim3 grid(GRAPH_DIM / P_BN, cdiv(N_NODES, GBM));
        bf16x3_gemm_pre<<<grid, 256, P_SMEM>>>(x_hi, x_lo, IN_DIM_PAD,
                                               wgt_hi, wgt_lo, bg, h, GRAPH_DIM, N_NODES);
    }

    // 2) SpMM (CSR, smem-staged)
    spmm_csr<<<N_NODES, 128>>>(rowstart, edges, h, agg);

    // 3) BN0 stats + coefficients
    colstats<GRAPH_DIM><<<dim3(GRAPH_DIM / 256, cdiv(N_NODES, 512)), 256>>>(agg, st0, N_NODES, 512);
    bn_coeffs<GRAPH_DIM><<<GRAPH_DIM / 256, 256>>>(st0, gamma0, beta0, sc0, sh0, N_NODES);

    // 4) h1pre = softplus(bn(agg)) @ W1 + b1  (fused BN0 loader)
    {
        dim3 grid(1, cdiv(N_NODES, GBM));
        bf16x3_gemm<256><<<grid, 256, SMEM256>>>(agg, GRAPH_DIM, GRAPH_DIM, GRAPH_DIM,
                                                 w1t_hi, w1t_lo, b1, h1, HIDDEN_DIM, N_NODES, 0,
                                                 sc0, sh0);
    }

    // 5) BN1 stats + coefficients
    colstats<HIDDEN_DIM><<<dim3(1, cdiv(N_NODES, 512)), 256>>>(h1, st1, N_NODES, 512);
    bn_coeffs<HIDDEN_DIM><<<1, HIDDEN_DIM>>>(st1, gamma1, beta1, sc1, sh1, N_NODES);

    // 6) [mu | logvar] = softplus(bn(h1pre)) @ [W21|W22] + blat  (fused BN1)
    {
        dim3 grid(1, cdiv(N_NODES, GBM));
        bf16x3_gemm<128><<<grid, 256, SMEM128>>>(h1, HIDDEN_DIM, HIDDEN_DIM, HIDDEN_DIM,
                                                 wlat_hi, wlat_lo, blat, out, 0, N_NODES, 1,
                                                 sc1, sh1);
    }
    (void)in_sizes; (void)n_in; (void)out_size;
}

// round 8
// speedup vs baseline: 1.1325x; 1.1325x over previous
#include <cuda_runtime.h>
#include <cuda_bf16.h>
#include <cstdint>

#define N_NODES 50000
#define IN_DIM 2000
#define IN_DIM_PAD 2048
#define GRAPH_DIM 512
#define HIDDEN_DIM 256
#define LATENT_DIM 64
#define N_EDGES 1600000
#define BN_EPS 1e-5f

// Scratch (device globals; allocation is forbidden)
__device__ float g_h[(size_t)N_NODES * GRAPH_DIM];
__device__ float g_agg[(size_t)N_NODES * GRAPH_DIM];
__device__ float g_h1[(size_t)N_NODES * HIDDEN_DIM];
__device__ float g_stats0[2 * GRAPH_DIM];
__device__ float g_stats1[2 * HIDDEN_DIM];
__device__ float g_sc0[GRAPH_DIM], g_sh0[GRAPH_DIM];
__device__ float g_sc1[HIDDEN_DIM], g_sh1[HIDDEN_DIM];
// CSR scratch
__device__ int g_rowcnt[N_NODES];
__device__ int g_rowstart[N_NODES + 1];
__device__ int g_cursor[N_NODES];
__device__ int2 g_edges[N_EDGES];
// Pre-transposed + bf16-split weights: [Nc][Kpad]
__device__ __nv_bfloat16 g_WgT_hi[(size_t)GRAPH_DIM * IN_DIM_PAD];
__device__ __nv_bfloat16 g_WgT_lo[(size_t)GRAPH_DIM * IN_DIM_PAD];
__device__ __nv_bfloat16 g_W1T_hi[(size_t)HIDDEN_DIM * GRAPH_DIM];
__device__ __nv_bfloat16 g_W1T_lo[(size_t)HIDDEN_DIM * GRAPH_DIM];
__device__ __nv_bfloat16 g_WlatT_hi[(size_t)128 * HIDDEN_DIM];
__device__ __nv_bfloat16 g_WlatT_lo[(size_t)128 * HIDDEN_DIM];
__device__ float g_blat[128];

static inline int cdiv(int a, int b) { return (a + b - 1) / b; }

// ---------------------------------------------------------------------------
// PTX helpers
// ---------------------------------------------------------------------------
__device__ __forceinline__ uint32_t smem_u32(const void* p) {
    uint32_t a;
    asm("{ .reg .u64 t; cvta.to.shared.u64 t, %1; cvt.u32.u64 %0, t; }" : "=r"(a) : "l"(p));
    return a;
}
__device__ __forceinline__ void ldsm4(uint32_t* d, uint32_t addr) {
    asm volatile("ldmatrix.sync.aligned.m8n8.x4.shared.b16 {%0,%1,%2,%3}, [%4];"
                 : "=r"(d[0]), "=r"(d[1]), "=r"(d[2]), "=r"(d[3]) : "r"(addr));
}
__device__ __forceinline__ void mma_bf16(float* c, const uint32_t* a, const uint32_t* b) {
    asm volatile(
        "mma.sync.aligned.m16n8k16.row.col.f32.bf16.bf16.f32 "
        "{%0,%1,%2,%3}, {%4,%5,%6,%7}, {%8,%9}, {%0,%1,%2,%3};"
        : "+f"(c[0]), "+f"(c[1]), "+f"(c[2]), "+f"(c[3])
        : "r"(a[0]), "r"(a[1]), "r"(a[2]), "r"(a[3]), "r"(b[0]), "r"(b[1]));
}
__device__ __forceinline__ void cp16(uint32_t dst, const void* src) {
    asm volatile("cp.async.cg.shared.global [%0], [%1], 16;" :: "r"(dst), "l"(src));
}
#define CP_COMMIT() asm volatile("cp.async.commit_group;" ::: "memory")
#define CP_WAIT0()  asm volatile("cp.async.wait_group 0;" ::: "memory")

__device__ __forceinline__ uint32_t pack_bf16x2(__nv_bfloat16 lo, __nv_bfloat16 hi) {
    return ((uint32_t)__bfloat16_as_ushort(hi) << 16) | (uint32_t)__bfloat16_as_ushort(lo);
}
__device__ __forceinline__ float softplus_f(float x) {
    return fmaxf(x, 0.f) + log1pf(expf(-fabsf(x)));
}

// ---------------------------------------------------------------------------
// Weight transpose + bf16 split
// ---------------------------------------------------------------------------
__global__ void split_w_bf16(const float* __restrict__ W, __nv_bfloat16* __restrict__ Thi,
                             __nv_bfloat16* __restrict__ Tlo, int K, int Nc, int Kpad)
{
    int idx = blockIdx.x * blockDim.x + threadIdx.x;
    if (idx >= Nc * Kpad) return;
    int n = idx / Kpad;
    int k = idx % Kpad;
    float v = (k < K) ? W[(size_t)k * Nc + n] : 0.f;
    __nv_bfloat16 hi = __float2bfloat16(v);
    __nv_bfloat16 lo = __float2bfloat16(v - __bfloat162float(hi));
    Thi[idx] = hi;
    Tlo[idx] = lo;
}

__global__ void concat_bias(const float* __restrict__ b21, const float* __restrict__ b22,
                            float* __restrict__ blat)
{
    int t = threadIdx.x;
    if (t < 64) blat[t] = b21[t];
    else if (t < 128) blat[t] = b22[t - 64];
}

// ---------------------------------------------------------------------------
// Shared GEMM geometry
// ---------------------------------------------------------------------------
#define GBM 128
#define ROWB 80
#define TILEA (GBM * ROWB)   // 10240

// ---------------------------------------------------------------------------
// GEMM1: 512 threads (16 warps, warptile 32x64), tile 128x256xK32, 2-stage.
//   fp32 A loader with on-the-fly bf16 hi/lo split (R6-style), pre-split B.
// ---------------------------------------------------------------------------
#define G1_BN 256
#define G1_BTILE (G1_BN * ROWB)               // 20480
#define G1_OB (2 * TILEA)
#define G1_STAGE (2 * TILEA + 2 * G1_BTILE)   // 61440
#define G1_SMEM (2 * G1_STAGE)                // 122880

__global__ void __launch_bounds__(512)
g1_gemm(const float* __restrict__ A, int lda, int Kvalid, int Kpad,
        const __nv_bfloat16* __restrict__ Bhi, const __nv_bfloat16* __restrict__ Blo,
        const float* __restrict__ bias, float* __restrict__ C, int ldc, int M)
{
    extern __shared__ char sm[];
    const uint32_t smb = smem_u32(sm);

    const int tid = threadIdx.x;
    const int lane = tid & 31;
    const int wid = tid >> 5;            // 0..15
    const int warpM = wid >> 2;          // 0..3  (32 rows each)
    const int warpN = wid & 3;           // 0..3  (64 cols each)
    const int rowBase = blockIdx.y * GBM;
    const int colBase = blockIdx.x * G1_BN;
    const int nIter = Kpad / 32;

    float acc[2][8][4];
#pragma unroll
    for (int i = 0; i < 2; i++)
#pragma unroll
        for (int j = 0; j < 8; j++)
#pragma unroll
            for (int v = 0; v < 4; v++) acc[i][j][v] = 0.f;

    // A loader: 1024 fp32 quads, 2 per thread
    float4 av[2];
    int arow[2], akq[2];
#pragma unroll
    for (int q = 0; q < 2; q++) {
        int qi = tid + q * 512;
        arow[q] = qi >> 3;
        akq[q] = qi & 7;
    }

    auto loadA = [&](int it) {
        int k0 = it * 32;
#pragma unroll
        for (int q = 0; q < 2; q++) {
            int gr = rowBase + arow[q];
            int k = k0 + akq[q] * 4;
            float4 v = make_float4(0.f, 0.f, 0.f, 0.f);
            if (gr < M) {
                const float* src = A + (size_t)gr * lda + k;
                if (k + 3 < Kvalid) {
                    v = *(const float4*)src;
                } else if (k < Kvalid) {
                    v.x = src[0];
                    if (k + 1 < Kvalid) v.y = src[1];
                    if (k + 2 < Kvalid) v.z = src[2];
                }
            }
            av[q] = v;
        }
    };

    auto stsA = [&](int stage) {
        char* sp = sm + stage * G1_STAGE;
#pragma unroll
        for (int q = 0; q < 2; q++) {
            float4 v = av[q];
            __nv_bfloat16 h0 = __float2bfloat16(v.x);
            __nv_bfloat16 h1 = __float2bfloat16(v.y);
            __nv_bfloat16 h2 = __float2bfloat16(v.z);
            __nv_bfloat16 h3 = __float2bfloat16(v.w);
            __nv_bfloat16 l0 = __float2bfloat16(v.x - __bfloat162float(h0));
            __nv_bfloat16 l1 = __float2bfloat16(v.y - __bfloat162float(h1));
            __nv_bfloat16 l2 = __float2bfloat16(v.z - __bfloat162float(h2));
            __nv_bfloat16 l3 = __float2bfloat16(v.w - __bfloat162float(h3));
            uint2 hp = make_uint2(pack_bf16x2(h0, h1), pack_bf16x2(h2, h3));
            uint2 lp = make_uint2(pack_bf16x2(l0, l1), pack_bf16x2(l2, l3));
            int off = arow[q] * ROWB + akq[q] * 8;
            *(uint2*)(sp + off) = hp;
            *(uint2*)(sp + TILEA + off) = lp;
        }
    };

    auto cpB = [&](int it, int stage) {
        int k0 = it * 32;
#pragma unroll
        for (int q = 0; q < 4; q++) {       // 2048 chunks / 512 threads
            int ci = tid + q * 512;
            int hilo = ci >> 10;
            int row = (ci >> 2) & 255;
            int c = ci & 3;
            const __nv_bfloat16* src =
                (hilo ? Blo : Bhi) + (size_t)(colBase + row) * Kpad + k0 + c * 8;
            uint32_t dst = smb + stage * G1_STAGE + G1_OB + hilo * G1_BTILE
                           + row * ROWB + c * 16;
            cp16(dst, src);
        }
    };

    const uint32_t aLaneOff = (uint32_t)((lane & 15) * ROWB + ((lane >> 4) << 4));
    const uint32_t bLaneOff = (uint32_t)(((lane & 7) + ((lane & 16) >> 1)) * ROWB
                                         + (((lane >> 3) & 1) << 4));

    loadA(0);
    cpB(0, 0);
    CP_COMMIT();
    stsA(0);

    for (int it = 0; it < nIter; ++it) {
        const int cur = it & 1;
        const int nxt = cur ^ 1;
        const bool more = (it + 1 < nIter);
        if (more) loadA(it + 1);
        CP_WAIT0();
        __syncthreads();
        if (more) {
            stsA(nxt);
            cpB(it + 1, nxt);
            CP_COMMIT();
        }

        const uint32_t aBase = smb + cur * G1_STAGE + warpM * 32 * ROWB + aLaneOff;
        const uint32_t bBase = smb + cur * G1_STAGE + G1_OB + warpN * 64 * ROWB + bLaneOff;
#pragma unroll
        for (int ks = 0; ks < 2; ks++) {
            const uint32_t kb = ks * 32;
            uint32_t bH[4][4], bL[4][4], aF[2][4];
#pragma unroll
            for (int g = 0; g < 4; g++) {
                ldsm4(bH[g], bBase + g * 16 * ROWB + kb);
                ldsm4(bL[g], bBase + G1_BTILE + g * 16 * ROWB + kb);
            }
#pragma unroll
            for (int mt = 0; mt < 2; mt++) ldsm4(aF[mt], aBase + mt * 16 * ROWB + kb);
#pragma unroll
            for (int mt = 0; mt < 2; mt++)
#pragma unroll
                for (int nt = 0; nt < 8; nt++)
                    mma_bf16(acc[mt][nt], aF[mt], &bH[nt >> 1][(nt & 1) * 2]);
#pragma unroll
            for (int mt = 0; mt < 2; mt++)
#pragma unroll
                for (int nt = 0; nt < 8; nt++)
                    mma_bf16(acc[mt][nt], aF[mt], &bL[nt >> 1][(nt & 1) * 2]);
#pragma unroll
            for (int mt = 0; mt < 2; mt++) ldsm4(aF[mt], aBase + TILEA + mt * 16 * ROWB + kb);
#pragma unroll
            for (int mt = 0; mt < 2; mt++)
#pragma unroll
                for (int nt = 0; nt < 8; nt++)
                    mma_bf16(acc[mt][nt], aF[mt], &bH[nt >> 1][(nt & 1) * 2]);
        }
    }

    const int r0 = rowBase + warpM * 32 + (lane >> 2);
    const int c0 = colBase + warpN * 64 + (lane & 3) * 2;
#pragma unroll
    for (int mt = 0; mt < 2; mt++) {
#pragma unroll
        for (int nt = 0; nt < 8; nt++) {
            int r = r0 + mt * 16;
            int c = c0 + nt * 8;
            float b0 = bias[c], b1 = bias[c + 1];
            if (r < M)
                *(float2*)&C[(size_t)r * ldc + c] =
                    make_float2(acc[mt][nt][0] + b0, acc[mt][nt][1] + b1);
            if (r + 8 < M)
                *(float2*)&C[(size_t)(r + 8) * ldc + c] =
                    make_float2(acc[mt][nt][2] + b0, acc[mt][nt][3] + b1);
        }
    }
}

// ---------------------------------------------------------------------------
// bf16x3 GEMM (256 threads) with fp32 A + optional fused BN+softplus loader.
// ---------------------------------------------------------------------------
template <int BN>
__global__ void __launch_bounds__(256)
bf16x3_gemm(const float* __restrict__ A, int lda, int Kvalid, int Kpad,
            const __nv_bfloat16* __restrict__ Bhi, const __nv_bfloat16* __restrict__ Blo,
            const float* __restrict__ bias, float* __restrict__ C, int ldc,
            int M, int latent,
            const float* __restrict__ Ascale, const float* __restrict__ Ashift)
{
    constexpr int BTILE = BN * ROWB;
    constexpr int OB = 2 * TILEA;
    constexpr int STAGE = 2 * TILEA + 2 * BTILE;
    constexpr int NT = BN / 32;
    constexpr int NLD = BN / 64;
    constexpr int BCHUNKS = BN / 32;

    extern __shared__ char sm[];
    const uint32_t smb = smem_u32(sm);

    const int tid = threadIdx.x;
    const int lane = tid & 31;
    const int wid = tid >> 5;
    const int warpM = wid >> 2;
    const int warpN = wid & 3;
    const int rowBase = blockIdx.y * GBM;
    const int colBase = blockIdx.x * BN;
    const int nIter = Kpad / 32;
    const bool fuse = (Ascale != nullptr);

    float acc[4][NT][4];
#pragma unroll
    for (int i = 0; i < 4; i++)
#pragma unroll
        for (int j = 0; j < NT; j++)
#pragma unroll
            for (int v = 0; v < 4; v++) acc[i][j][v] = 0.f;

    float4 av[4];
    int arow[4], akq[4];
#pragma unroll
    for (int q = 0; q < 4; q++) {
        int qi = tid + q * 256;
        arow[q] = qi >> 3;
        akq[q] = qi & 7;
    }

    auto loadA = [&](int it) {
        int k0 = it * 32;
#pragma unroll
        for (int q = 0; q < 4; q++) {
            int gr = rowBase + arow[q];
            int k = k0 + akq[q] * 4;
            float4 v = make_float4(0.f, 0.f, 0.f, 0.f);
            if (gr < M) {
                const float* src = A + (size_t)gr * lda + k;
                if (k + 3 < Kvalid) {
                    v = *(const float4*)src;
                    if (fuse) {
                        v.x = softplus_f(v.x * __ldg(&Ascale[k + 0]) + __ldg(&Ashift[k + 0]));
                        v.y = softplus_f(v.y * __ldg(&Ascale[k + 1]) + __ldg(&Ashift[k + 1]));
                        v.z = softplus_f(v.z * __ldg(&Ascale[k + 2]) + __ldg(&Ashift[k + 2]));
                        v.w = softplus_f(v.w * __ldg(&Ascale[k + 3]) + __ldg(&Ashift[k + 3]));
                    }
                } else if (k < Kvalid) {
                    float* vp = &v.x;
#pragma unroll
                    for (int j = 0; j < 4; j++) {
                        if (k + j < Kvalid) {
                            float t = src[j];
                            if (fuse)
                                t = softplus_f(t * __ldg(&Ascale[k + j]) + __ldg(&Ashift[k + j]));
                            vp[j] = t;
                        }
                    }
                }
            }
            av[q] = v;
        }
    };

    auto stsA = [&](int stage) {
        char* sp = sm + stage * STAGE;
#pragma unroll
        for (int q = 0; q < 4; q++) {
            float4 v = av[q];
            __nv_bfloat16 h0 = __float2bfloat16(v.x);
            __nv_bfloat16 h1 = __float2bfloat16(v.y);
            __nv_bfloat16 h2 = __float2bfloat16(v.z);
            __nv_bfloat16 h3 = __float2bfloat16(v.w);
            __nv_bfloat16 l0 = __float2bfloat16(v.x - __bfloat162float(h0));
            __nv_bfloat16 l1 = __float2bfloat16(v.y - __bfloat162float(h1));
            __nv_bfloat16 l2 = __float2bfloat16(v.z - __bfloat162float(h2));
            __nv_bfloat16 l3 = __float2bfloat16(v.w - __bfloat162float(h3));
            uint2 hp = make_uint2(pack_bf16x2(h0, h1), pack_bf16x2(h2, h3));
            uint2 lp = make_uint2(pack_bf16x2(l0, l1), pack_bf16x2(l2, l3));
            int off = arow[q] * ROWB + akq[q] * 8;
            *(uint2*)(sp + off) = hp;
            *(uint2*)(sp + TILEA + off) = lp;
        }
    };

    auto cpB = [&](int it, int stage) {
        int k0 = it * 32;
#pragma unroll
        for (int q = 0; q < BCHUNKS; q++) {
            int ci = tid + q * 256;
            int hilo = ci / (BN * 4);
            int row = (ci >> 2) & (BN - 1);
            int c = ci & 3;
            const __nv_bfloat16* src =
                (hilo ? Blo : Bhi) + (size_t)(colBase + row) * Kpad + k0 + c * 8;
            uint32_t dst = smb + stage * STAGE + OB + hilo * BTILE + row * ROWB + c * 16;
            cp16(dst, src);
        }
    };

    const uint32_t aLaneOff = (uint32_t)((lane & 15) * ROWB + ((lane >> 4) << 4));
    const uint32_t bLaneOff = (uint32_t)(((lane & 7) + ((lane & 16) >> 1)) * ROWB
                                         + (((lane >> 3) & 1) << 4));

    loadA(0);
    cpB(0, 0);
    CP_COMMIT();
    stsA(0);

    for (int it = 0; it < nIter; ++it) {
        const int cur = it & 1;
        const int nxt = cur ^ 1;
        const bool more = (it + 1 < nIter);
        if (more) loadA(it + 1);
        CP_WAIT0();
        __syncthreads();
        if (more) {
            stsA(nxt);
            cpB(it + 1, nxt);
            CP_COMMIT();
        }

        const uint32_t aBase = smb + cur * STAGE + warpM * 64 * ROWB + aLaneOff;
        const uint32_t bBase = smb + cur * STAGE + OB + warpN * (BN / 4) * ROWB + bLaneOff;
#pragma unroll
        for (int ks = 0; ks < 2; ks++) {
            const uint32_t kb = ks * 32;
            uint32_t bH[NLD][4], bL[NLD][4], aF[4][4];
#pragma unroll
            for (int g = 0; g < NLD; g++) {
                ldsm4(bH[g], bBase + g * 16 * ROWB + kb);
                ldsm4(bL[g], bBase + BTILE + g * 16 * ROWB + kb);
            }
#pragma unroll
            for (int mt = 0; mt < 4; mt++) ldsm4(aF[mt], aBase + mt * 16 * ROWB + kb);
#pragma unroll
            for (int mt = 0; mt < 4; mt++)
#pragma unroll
                for (int nt = 0; nt < NT; nt++)
                    mma_bf16(acc[mt][nt], aF[mt], &bH[nt >> 1][(nt & 1) * 2]);
#pragma unroll
            for (int mt = 0; mt < 4; mt++)
#pragma unroll
                for (int nt = 0; nt < NT; nt++)
                    mma_bf16(acc[mt][nt], aF[mt], &bL[nt >> 1][(nt & 1) * 2]);
#pragma unroll
            for (int mt = 0; mt < 4; mt++) ldsm4(aF[mt], aBase + TILEA + mt * 16 * ROWB + kb);
#pragma unroll
            for (int mt = 0; mt < 4; mt++)
#pragma unroll
                for (int nt = 0; nt < NT; nt++)
                    mma_bf16(acc[mt][nt], aF[mt], &bH[nt >> 1][(nt & 1) * 2]);
        }
    }

    const int r0 = rowBase + warpM * 64 + (lane >> 2);
    const int c0 = colBase + warpN * (BN / 4) + (lane & 3) * 2;
#pragma unroll
    for (int mt = 0; mt < 4; mt++) {
#pragma unroll
        for (int nt = 0; nt < NT; nt++) {
            int r = r0 + mt * 16;
            int c = c0 + nt * 8;
            float b0 = bias[c], b1 = bias[c + 1];
            float v0 = acc[mt][nt][0] + b0;
            float v1 = acc[mt][nt][1] + b1;
            float v2 = acc[mt][nt][2] + b0;
            float v3 = acc[mt][nt][3] + b1;
            if (!latent) {
                if (r < M) *(float2*)&C[(size_t)r * ldc + c] = make_float2(v0, v1);
                if (r + 8 < M) *(float2*)&C[(size_t)(r + 8) * ldc + c] = make_float2(v2, v3);
            } else {
                float* base = (c < 64) ? C + c : C + (size_t)N_NODES * 64 + (c - 64);
                if (r < M) *(float2*)&base[(size_t)r * 64] = make_float2(v0, v1);
                if (r + 8 < M) *(float2*)&base[(size_t)(r + 8) * 64] = make_float2(v2, v3);
            }
        }
    }
}

// ---------------------------------------------------------------------------
// Zero kernels
// ---------------------------------------------------------------------------
__global__ void zero_kernel(float4* __restrict__ p, long long n4) {
    long long i = (long long)blockIdx.x * blockDim.x + threadIdx.x;
    long long stride = (long long)gridDim.x * blockDim.x;
    float4 z = make_float4(0.f, 0.f, 0.f, 0.f);
    for (; i < n4; i += stride) p[i] = z;
}
__global__ void zero_int(int* __restrict__ p, int n) {
    int i = blockIdx.x * blockDim.x + threadIdx.x;
    if (i < n) p[i] = 0;
}

// ---------------------------------------------------------------------------
// CSR build: histogram -> scan -> scatter
// ---------------------------------------------------------------------------
__global__ void csr_hist(const int* __restrict__ rows, int* __restrict__ cnt) {
    int e = blockIdx.x * blockDim.x + threadIdx.x;
    if (e < N_EDGES) atomicAdd(&cnt[rows[e]], 1);
}

__global__ void __launch_bounds__(1024)
csr_scan(const int* __restrict__ cnt, int* __restrict__ rowstart, int* __restrict__ cursor)
{
    __shared__ int warpsum[32];
    const int t = threadIdx.x;
    const int CH = (N_NODES + 1023) / 1024;
    const int base = t * CH;

    int s = 0;
    for (int i = 0; i < CH; i++) {
        int idx = base + i;
        if (idx < N_NODES) s += cnt[idx];
    }
    int lane = t & 31, w = t >> 5;
    int v = s;
#pragma unroll
    for (int o = 1; o < 32; o <<= 1) {
        int n = __shfl_up_sync(0xffffffffu, v, o);
        if (lane >= o) v += n;
    }
    if (lane == 31) warpsum[w] = v;
    __syncthreads();
    if (w == 0) {
        int x = warpsum[lane];
#pragma unroll
        for (int o = 1; o < 32; o <<= 1) {
            int n = __shfl_up_sync(0xffffffffu, x, o);
            if (lane >= o) x += n;
        }
        warpsum[lane] = x;
    }
    __syncthreads();
    int run = v - s + (w > 0 ? warpsum[w - 1] : 0);
    for (int i = 0; i < CH; i++) {
        int idx = base + i;
        if (idx < N_NODES) {
            rowstart[idx] = run;
            cursor[idx] = run;
            run += cnt[idx];
        }
    }
    if (t == 1023) rowstart[N_NODES] = N_EDGES;
}

__global__ void csr_scatter(const int* __restrict__ rows, const int* __restrict__ cols,
                            const float* __restrict__ vals, int* __restrict__ cursor,
                            int2* __restrict__ edges)
{
    int e = blockIdx.x * blockDim.x + threadIdx.x;
    if (e >= N_EDGES) return;
    int r = rows[e];
    int p = atomicAdd(&cursor[r], 1);
    edges[p] = make_int2(cols[e], __float_as_int(vals[e]));
}

// ---------------------------------------------------------------------------
// CSR SpMM with smem-staged edges + 4-deep independent gathers.
// ---------------------------------------------------------------------------
__global__ void __launch_bounds__(128)
spmm_csr(const int* __restrict__ rowstart, const int2* __restrict__ edges,
         const float* __restrict__ h, float* __restrict__ agg)
{
    __shared__ int2 se[128];
    const int r = blockIdx.x;
    const int t = threadIdx.x;
    const int s = rowstart[r];
    const int e = rowstart[r + 1];
    const float4* hp = (const float4*)h;

    float4 a0 = make_float4(0.f, 0.f, 0.f, 0.f);
    float4 a1 = make_float4(0.f, 0.f, 0.f, 0.f);
    float4 a2 = make_float4(0.f, 0.f, 0.f, 0.f);
    float4 a3 = make_float4(0.f, 0.f, 0.f, 0.f);

    for (int base = s; base < e; base += 128) {
        const int n = min(128, e - base);
        if (t < n) se[t] = __ldg(&edges[base + t]);
        __syncthreads();

        int i = 0;
        for (; i + 4 <= n; i += 4) {
            int2 e0 = se[i], e1 = se[i + 1], e2 = se[i + 2], e3 = se[i + 3];
            float4 h0 = __ldg(&hp[(size_t)e0.x * 128 + t]);
            float4 h1 = __ldg(&hp[(size_t)e1.x * 128 + t]);
            float4 h2 = __ldg(&hp[(size_t)e2.x * 128 + t]);
            float4 h3 = __ldg(&hp[(size_t)e3.x * 128 + t]);
            float v0 = __int_as_float(e0.y), v1 = __int_as_float(e1.y);
            float v2 = __int_as_float(e2.y), v3 = __int_as_float(e3.y);
            a0.x += v0 * h0.x; a0.y += v0 * h0.y; a0.z += v0 * h0.z; a0.w += v0 * h0.w;
            a1.x += v1 * h1.x; a1.y += v1 * h1.y; a1.z += v1 * h1.z; a1.w += v1 * h1.w;
            a2.x += v2 * h2.x; a2.y += v2 * h2.y; a2.z += v2 * h2.z; a2.w += v2 * h2.w;
            a3.x += v3 * h3.x; a3.y += v3 * h3.y; a3.z += v3 * h3.z; a3.w += v3 * h3.w;
        }
        for (; i < n; i++) {
            int2 e0 = se[i];
            float4 h0 = __ldg(&hp[(size_t)e0.x * 128 + t]);
            float v0 = __int_as_float(e0.y);
            a0.x += v0 * h0.x; a0.y += v0 * h0.y; a0.z += v0 * h0.z; a0.w += v0 * h0.w;
        }
        __syncthreads();
    }

    float4 o;
    o.x = (a0.x + a1.x) + (a2.x + a3.x);
    o.y = (a0.y + a1.y) + (a2.y + a3.y);
    o.z = (a0.z + a1.z) + (a2.z + a3.z);
    o.w = (a0.w + a1.w) + (a2.w + a3.w);
    ((float4*)agg)[(size_t)r * 128 + t] = o;
}

// ---------------------------------------------------------------------------
// Column statistics + BN coefficient computation
// ---------------------------------------------------------------------------
template <int C>
__global__ void colstats(const float* __restrict__ X, float* __restrict__ stats,
                         int Nrows, int rowsPerBlock)
{
    int col = blockIdx.x * blockDim.x + threadIdx.x;
    if (col >= C) return;
    int r0 = blockIdx.y * rowsPerBlock;
    int r1 = min(r0 + rowsPerBlock, Nrows);
    float s = 0.f, s2 = 0.f;
    for (int r = r0; r < r1; r++) {
        float v = X[(size_t)r * C + col];
        s += v;
        s2 += v * v;
    }
    atomicAdd(&stats[col], s);
    atomicAdd(&stats[C + col], s2);
}

template <int C>
__global__ void bn_coeffs(const float* __restrict__ stats, const float* __restrict__ gamma,
                          const float* __restrict__ beta, float* __restrict__ scale,
                          float* __restrict__ shift, int Nrows)
{
    int c = blockIdx.x * blockDim.x + threadIdx.x;
    if (c >= C) return;
    const float invN = 1.f / (float)Nrows;
    float mean = stats[c] * invN;
    float var = stats[C + c] * invN - mean * mean;
    float sc = rsqrtf(var + BN_EPS) * gamma[c];
    scale[c] = sc;
    shift[c] = beta[c] - mean * sc;
}

// ---------------------------------------------------------------------------
// Launcher
// ---------------------------------------------------------------------------
extern "C" void kernel_launch(void* const* d_in, const int* in_sizes, int n_in,
                              void* d_out, int out_size)
{
    const float* x        = (const float*)d_in[0];
    const int*   adj_rows = (const int*)d_in[1];
    const int*   adj_cols = (const int*)d_in[2];
    const float* adj_vals = (const float*)d_in[3];
    const float* Wg  = (const float*)d_in[4];
    const float* bg  = (const float*)d_in[5];
    const float* W1  = (const float*)d_in[6];
    const float* b1  = (const float*)d_in[7];
    const float* W21 = (const float*)d_in[8];
    const float* b21 = (const float*)d_in[9];
    const float* W22 = (const float*)d_in[10];
    const float* b22 = (const float*)d_in[11];
    const float* gamma0 = (const float*)d_in[12];
    const float* beta0  = (const float*)d_in[13];
    const float* gamma1 = (const float*)d_in[14];
    const float* beta1  = (const float*)d_in[15];
    float* out = (float*)d_out;

    float *h, *agg, *h1, *st0, *st1, *blat, *sc0, *sh0, *sc1, *sh1;
    int *rowcnt, *rowstart, *cursor;
    int2 *edges;
    __nv_bfloat16 *wgt_hi, *wgt_lo, *w1t_hi, *w1t_lo, *wlat_hi, *wlat_lo;
    cudaGetSymbolAddress((void**)&h,   g_h);
    cudaGetSymbolAddress((void**)&agg, g_agg);
    cudaGetSymbolAddress((void**)&h1,  g_h1);
    cudaGetSymbolAddress((void**)&st0, g_stats0);
    cudaGetSymbolAddress((void**)&st1, g_stats1);
    cudaGetSymbolAddress((void**)&blat, g_blat);
    cudaGetSymbolAddress((void**)&sc0, g_sc0);
    cudaGetSymbolAddress((void**)&sh0, g_sh0);
    cudaGetSymbolAddress((void**)&sc1, g_sc1);
    cudaGetSymbolAddress((void**)&sh1, g_sh1);
    cudaGetSymbolAddress((void**)&rowcnt, g_rowcnt);
    cudaGetSymbolAddress((void**)&rowstart, g_rowstart);
    cudaGetSymbolAddress((void**)&cursor, g_cursor);
    cudaGetSymbolAddress((void**)&edges, g_edges);
    cudaGetSymbolAddress((void**)&wgt_hi, g_WgT_hi);
    cudaGetSymbolAddress((void**)&wgt_lo, g_WgT_lo);
    cudaGetSymbolAddress((void**)&w1t_hi, g_W1T_hi);
    cudaGetSymbolAddress((void**)&w1t_lo, g_W1T_lo);
    cudaGetSymbolAddress((void**)&wlat_hi, g_WlatT_hi);
    cudaGetSymbolAddress((void**)&wlat_lo, g_WlatT_lo);

    constexpr int SMEM128 = 2 * (2 * TILEA + 2 * 128 * ROWB);  //  81920
    constexpr int SMEM256 = 2 * (2 * TILEA + 2 * 256 * ROWB);  // 122880
    cudaFuncSetAttribute(bf16x3_gemm<128>, cudaFuncAttributeMaxDynamicSharedMemorySize, SMEM128);
    cudaFuncSetAttribute(bf16x3_gemm<256>, cudaFuncAttributeMaxDynamicSharedMemorySize, SMEM256);
    cudaFuncSetAttribute(g1_gemm, cudaFuncAttributeMaxDynamicSharedMemorySize, G1_SMEM);

    // --- launch order puts GEMM1 at position 4 so ncu captures it ---

    // 1-2) stats zero
    zero_kernel<<<1, 256>>>((float4*)st0, 2 * GRAPH_DIM / 4);
    zero_kernel<<<1, 256>>>((float4*)st1, 2 * HIDDEN_DIM / 4);

    // 3) Wg split (GEMM1's only dependency)
    {
        int totWg = GRAPH_DIM * IN_DIM_PAD;
        split_w_bf16<<<cdiv(totWg, 256), 256>>>(Wg, wgt_hi, wgt_lo, IN_DIM, GRAPH_DIM, IN_DIM_PAD);
    }

    // 4) GEMM1: h = x @ Wg + bg   (512-thread, 16-warp version)
    {
        dim3 grid(GRAPH_DIM / G1_BN, cdiv(N_NODES, GBM));
        g1_gemm<<<grid, 512, G1_SMEM>>>(x, IN_DIM, IN_DIM, IN_DIM_PAD,
                                        wgt_hi, wgt_lo, bg, h, GRAPH_DIM, N_NODES);
    }

    // 5+) CSR build + remaining weight prep (independent of GEMM1 output)
    zero_int<<<cdiv(N_NODES, 256), 256>>>(rowcnt, N_NODES);
    csr_hist<<<cdiv(N_EDGES, 256), 256>>>(adj_rows, rowcnt);
    csr_scan<<<1, 1024>>>(rowcnt, rowstart, cursor);
    csr_scatter<<<cdiv(N_EDGES, 256), 256>>>(adj_rows, adj_cols, adj_vals, cursor, edges);
    {
        int totW1 = HIDDEN_DIM * GRAPH_DIM;
        split_w_bf16<<<cdiv(totW1, 256), 256>>>(W1, w1t_hi, w1t_lo, GRAPH_DIM, HIDDEN_DIM, GRAPH_DIM);
        int totWl = 64 * HIDDEN_DIM;
        split_w_bf16<<<cdiv(totWl, 256), 256>>>(W21, wlat_hi, wlat_lo, HIDDEN_DIM, 64, HIDDEN_DIM);
        split_w_bf16<<<cdiv(totWl, 256), 256>>>(W22, wlat_hi + (size_t)64 * HIDDEN_DIM,
                                                wlat_lo + (size_t)64 * HIDDEN_DIM,
                                                HIDDEN_DIM, 64, HIDDEN_DIM);
        concat_bias<<<1, 128>>>(b21, b22, blat);
    }

    // SpMM (CSR, smem-staged)
    spmm_csr<<<N_NODES, 128>>>(rowstart, edges, h, agg);

    // BN0 stats + coefficients
    colstats<GRAPH_DIM><<<dim3(GRAPH_DIM / 256, cdiv(N_NODES, 512)), 256>>>(agg, st0, N_NODES, 512);
    bn_coeffs<GRAPH_DIM><<<GRAPH_DIM / 256, 256>>>(st0, gamma0, beta0, sc0, sh0, N_NODES);

    // GEMM2: h1pre = softplus(bn(agg)) @ W1 + b1  (fused BN0 loader)
    {
        dim3 grid(1, cdiv(N_NODES, GBM));
        bf16x3_gemm<256><<<grid, 256, SMEM256>>>(agg, GRAPH_DIM, GRAPH_DIM, GRAPH_DIM,
                                                 w1t_hi, w1t_lo, b1, h1, HIDDEN_DIM, N_NODES, 0,
                                                 sc0, sh0);
    }

    // BN1 stats + coefficients
    colstats<HIDDEN_DIM><<<dim3(1, cdiv(N_NODES, 512)), 256>>>(h1, st1, N_NODES, 512);
    bn_coeffs<HIDDEN_DIM><<<1, HIDDEN_DIM>>>(st1, gamma1, beta1, sc1, sh1, N_NODES);

    // Latent: [mu | logvar] = softplus(bn(h1pre)) @ [W21|W22] + blat  (fused BN1)
    {
        dim3 grid(1, cdiv(N_NODES, GBM));
        bf16x3_gemm<128><<<grid, 256, SMEM128>>>(h1, HIDDEN_DIM, HIDDEN_DIM, HIDDEN_DIM,
                                                 wlat_hi, wlat_lo, blat, out, 0, N_NODES, 1,
                                                 sc1, sh1);
    }
    (void)in_sizes; (void)n_in; (void)out_size;
}